// round 12
// baseline (speedup 1.0000x reference)
#include <cuda_runtime.h>
#include <math_constants.h>

#define N_IN   1024
#define N_OUT  4096
#define BF     64                   // BATCH * FEAT
#define NW     32                   // bitmap words per column (1024 bits)

// Device-global scratch (zero-initialized at module load; gather re-zeroes
// g_bits right after reading -> every graph replay sees identical state).
__device__ unsigned g_bits[N_OUT * NW];        // bitmap[m][w]: bit set <=> B[n,m]!=0
__device__ float    g_xt[N_IN * BF];           // xt[n][bf], 256B per row

// ---------------------------------------------------------------------------
// Kernel 1: linear float4 scan of B. 1024 blocks x 256 threads, 4 independent
// LDG.128 per thread preloaded up-front (16.8MB read once, coalesced).
// Nonzeros recorded with fire-and-forget atomicOr (return unused -> RED, no
// round-trip on the critical path). First 256 blocks also transpose x.
__global__ __launch_bounds__(256)
void scan_kernel(const float* __restrict__ B, const float* __restrict__ x)
{
    const int t = threadIdx.x;
    const int b = blockIdx.x;

    // Fold in the x transpose (no separate prep launch).
    if (b < 256) {
        int i  = b * 256 + t;                 // 0 .. 65535
        int bf = i >> 10;
        int n  = i & 1023;
        g_xt[n * BF + bf] = x[i];
    }

    const float4* B4 = (const float4*)B;
    const int base = b * 256 + t;
    float4 v[4];
    #pragma unroll
    for (int it = 0; it < 4; it++)
        v[it] = B4[base + it * (1024 * 256)];  // covers 2^20 float4 = 16.8MB

    #pragma unroll
    for (int it = 0; it < 4; it++) {
        if (v[it].x != 0.f || v[it].y != 0.f || v[it].z != 0.f || v[it].w != 0.f) {
            int      i4   = base + it * (1024 * 256);
            int      n    = i4 >> 10;          // 1024 float4 per row
            int      m0   = (i4 & 1023) << 2;
            unsigned bit  = 1u << (n & 31);
            int      word = n >> 5;
            float c[4] = {v[it].x, v[it].y, v[it].z, v[it].w};
            #pragma unroll
            for (int j = 0; j < 4; j++)
                if (c[j] != 0.f)
                    atomicOr(&g_bits[(m0 + j) * NW + word], bit);  // RED: no return
        }
    }
}

// ---------------------------------------------------------------------------
// Kernel 2: gather-max. 1024 blocks x 256 threads, one output element per
// thread (block = 4 columns x 64 bf). The 4 column bitmaps (512B) are staged
// into shared by 128 threads (coalesced) and immediately re-zeroed in global.
// Each thread walks the 32 words fully unrolled: every set bit issues an
// independent xt line-load into one of 4 rotating accumulators. Exact for ANY
// nonzero count: the 0 contribution is included iff total bits < N_IN.
__global__ __launch_bounds__(256)
void gather_kernel(float* __restrict__ y)
{
    __shared__ unsigned s_bits[4][NW];           // 512 B

    const int t   = threadIdx.x;
    const int g   = t >> 6;                      // column group 0..3
    const int col = blockIdx.x * 4 + g;
    const int bf  = t & 63;

    if (t < 4 * NW) {
        int gg = t >> 5, w = t & 31;
        size_t off = (size_t)(blockIdx.x * 4 + gg) * NW + w;
        unsigned v = g_bits[off];
        s_bits[gg][w] = v;
        g_bits[off] = 0;                         // replay reset (same-thread order)
    }
    __syncthreads();

    const float* xr = &g_xt[bf];
    float a0 = -CUDART_INF_F, a1 = -CUDART_INF_F;
    float a2 = -CUDART_INF_F, a3 = -CUDART_INF_F;
    int total = 0;

    #pragma unroll
    for (int w = 0; w < NW; w++) {
        unsigned bits = s_bits[g][w];
        total += __popc(bits);
        while (bits) {
            int bpos = __ffs(bits) - 1;
            bits &= bits - 1;
            float v = xr[(w * 32 + bpos) * BF];  // independent across words
            if      ((w & 3) == 0) a0 = fmaxf(a0, v);
            else if ((w & 3) == 1) a1 = fmaxf(a1, v);
            else if ((w & 3) == 2) a2 = fmaxf(a2, v);
            else                   a3 = fmaxf(a3, v);
        }
    }

    float acc = fmaxf(fmaxf(a0, a1), fmaxf(a2, a3));
    if (total < N_IN) acc = fmaxf(acc, 0.0f);    // a zero product participates
                                                 // exactly when count < N_IN
    y[(size_t)bf * N_OUT + col] = acc;
}

// ---------------------------------------------------------------------------
extern "C" void kernel_launch(void* const* d_in, const int* in_sizes, int n_in,
                              void* d_out, int out_size)
{
    const float* x = (const float*)d_in[0];   // (2, 32, 1024) f32
    const float* B = (const float*)d_in[1];   // (1024, 4096) f32
    float*       y = (float*)d_out;           // (2, 32, 4096) f32
    (void)in_sizes; (void)n_in; (void)out_size;

    scan_kernel  <<<1024, 256>>>(B, x);
    gather_kernel<<<1024, 256>>>(y);
}

// round 13
// speedup vs baseline: 1.3365x; 1.3365x over previous
#include <cuda_runtime.h>
#include <math_constants.h>

#define N_IN   1024
#define N_OUT  4096
#define BF     64                   // BATCH * FEAT
#define NW     32                   // bitmap words per column (1024 bits)

// Device-global scratch (zero-initialized at module load; gather re-zeroes
// g_bits right after reading -> every graph replay sees identical state).
// g_xt has ONE EXTRA ROW (index N_IN), never written: permanent zero row used
// as branch-free padding in the gather (max legitimately includes 0).
__device__ unsigned g_bits[N_OUT * NW];        // bitmap[m][w]: bit set <=> B[n,m]!=0
__device__ float    g_xt[(N_IN + 1) * BF];     // xt[n][bf], 256B per row

// ---------------------------------------------------------------------------
// Kernel 1: linear float4 scan of B. 1024 blocks x 256 threads, 4 independent
// LDG.128 per thread preloaded up-front (16.8MB read once, coalesced).
// Nonzeros recorded with fire-and-forget atomicOr (return unused -> RED, no
// round-trip on the critical path). First 256 blocks also transpose x.
__global__ __launch_bounds__(256)
void scan_kernel(const float* __restrict__ B, const float* __restrict__ x)
{
    const int t = threadIdx.x;
    const int b = blockIdx.x;

    // Fold in the x transpose (no separate prep launch).
    if (b < 256) {
        int i  = b * 256 + t;                 // 0 .. 65535
        int bf = i >> 10;
        int n  = i & 1023;
        g_xt[n * BF + bf] = x[i];
    }

    const float4* B4 = (const float4*)B;
    const int base = b * 256 + t;
    float4 v[4];
    #pragma unroll
    for (int it = 0; it < 4; it++)
        v[it] = B4[base + it * (1024 * 256)];  // covers 2^20 float4 = 16.8MB

    #pragma unroll
    for (int it = 0; it < 4; it++) {
        if (v[it].x != 0.f || v[it].y != 0.f || v[it].z != 0.f || v[it].w != 0.f) {
            int      i4   = base + it * (1024 * 256);
            int      n    = i4 >> 10;          // 1024 float4 per row
            int      m0   = (i4 & 1023) << 2;
            unsigned bit  = 1u << (n & 31);
            int      word = n >> 5;
            float c[4] = {v[it].x, v[it].y, v[it].z, v[it].w};
            #pragma unroll
            for (int j = 0; j < 4; j++)
                if (c[j] != 0.f)
                    atomicOr(&g_bits[(m0 + j) * NW + word], bit);  // RED: no return
        }
    }
}

// ---------------------------------------------------------------------------
// Kernel 2: gather-max. 1024 blocks x 256 threads, one output element per
// thread (block = 4 columns x 64 bf).
//   Step 1: stage 4 column bitmaps into shared (coalesced) + reset in global.
//   Step 2: warps 0-3 convert one bitmap each to an index list via popc +
//           shfl prefix scan (each lane emits its word's set bits at its
//           scanned offset). Exact for ANY count (s_idx holds 1024 entries).
//   Step 3: all 256 threads gather cnt independent xt line-loads, indices
//           from shared, padded with the permanent zero row.
__global__ __launch_bounds__(256)
void gather_kernel(float* __restrict__ y)
{
    __shared__ unsigned       s_bits[4][NW];     // 512 B
    __shared__ unsigned short s_idx[4][N_IN];    // 8 KB
    __shared__ int            s_cnt[4];

    const int t    = threadIdx.x;
    const int lane = t & 31;
    const int warp = t >> 5;
    const int g    = t >> 6;                     // column group 0..3
    const int col  = blockIdx.x * 4 + g;
    const int bf   = t & 63;

    if (t < 4 * NW) {
        int gg = t >> 5, w = t & 31;
        size_t off = (size_t)(blockIdx.x * 4 + gg) * NW + w;
        unsigned v = g_bits[off];
        s_bits[gg][w] = v;
        g_bits[off] = 0;                         // replay reset (same-thread order)
    }
    __syncthreads();

    // Warp-parallel bitmap -> index-list conversion (warps 0..3, lane = word).
    if (warp < 4) {
        unsigned bits = s_bits[warp][lane];
        int c = __popc(bits);
        int pre = c;                             // inclusive prefix over lanes
        #pragma unroll
        for (int d = 1; d < 32; d <<= 1) {
            int vv = __shfl_up_sync(0xffffffffu, pre, d);
            if (lane >= d) pre += vv;
        }
        int off = pre - c;                       // exclusive offset
        int nb  = lane << 5;                     // word base = lane*32
        while (bits) {
            int bpos = __ffs(bits) - 1;
            bits &= bits - 1;
            s_idx[warp][off++] = (unsigned short)(nb + bpos);
        }
        if (lane == 31) s_cnt[warp] = pre;       // total count
    }
    __syncthreads();

    const int cnt = s_cnt[g];
    const float* xr = &g_xt[bf];
    const unsigned short* il = s_idx[g];

    float acc = (cnt < N_IN) ? 0.0f : -CUDART_INF_F;  // zero product participates
                                                      // exactly when cnt < N_IN
    for (int k = 0; k < cnt; k += 8) {
        int id[8];
        #pragma unroll
        for (int j = 0; j < 8; j++)
            id[j] = (k + j < cnt) ? (int)il[k + j] : N_IN;   // zero-row pad
        float v[8];
        #pragma unroll
        for (int j = 0; j < 8; j++)              // 8 independent line loads
            v[j] = xr[id[j] * BF];
        #pragma unroll
        for (int j = 0; j < 8; j++)
            acc = fmaxf(acc, v[j]);
    }

    y[(size_t)bf * N_OUT + col] = acc;           // 4B/thread; sectors combine in L2
}

// ---------------------------------------------------------------------------
extern "C" void kernel_launch(void* const* d_in, const int* in_sizes, int n_in,
                              void* d_out, int out_size)
{
    const float* x = (const float*)d_in[0];   // (2, 32, 1024) f32
    const float* B = (const float*)d_in[1];   // (1024, 4096) f32
    float*       y = (float*)d_out;           // (2, 32, 4096) f32
    (void)in_sizes; (void)n_in; (void)out_size;

    scan_kernel  <<<1024, 256>>>(B, x);
    gather_kernel<<<1024, 256>>>(y);
}